// round 11
// baseline (speedup 1.0000x reference)
#include <cuda_runtime.h>
#include <cuda_bf16.h>
#include <cstdint>

#define B 8
#define C 128
#define HW 65536
#define K 64
#define NTOT 524288.0f
#define BN_EPS 1e-5f

// ---------------- scratch (device globals; no allocation allowed) ----------------
__device__ float g_G[C * C];                    // Gram matrix sum_p x x^T
__device__ float g_sums_x[B * K * C];           // segment sums of x
__device__ float g_cnt[B * K];                  // segment counts
__device__ float g_sumsq[C];                    // per-channel sum of xw^2
__device__ float g_means[B * K * C];
__device__ float g_M[C * C];                    // W @ W^T
__device__ float g_Y[B * K * C];                // means @ M
__device__ float g_adj[B * K * K];
__device__ float g_adjm[B * K * C];             // adj_nd @ means
__device__ float g_bias[B * C * K];             // [b][d][k] = s*adjm + t
__device__ float g_s[C];
__device__ float g_t[C];
__device__ __nv_bfloat16 g_wh[C * 132];         // w^T hi  [d][c], pitch 132
__device__ __nv_bfloat16 g_wl[C * 132];         // w^T lo

#define MMA_BF16(d, a, bb) \
    asm volatile("mma.sync.aligned.m16n8k16.row.col.f32.bf16.bf16.f32 " \
        "{%0,%1,%2,%3}, {%4,%5,%6,%7}, {%8,%9}, {%0,%1,%2,%3};" \
        : "+f"((d)[0]), "+f"((d)[1]), "+f"((d)[2]), "+f"((d)[3]) \
        : "r"((a)[0]), "r"((a)[1]), "r"((a)[2]), "r"((a)[3]), \
          "r"((bb)[0]), "r"((bb)[1]))

__device__ __forceinline__ uint32_t smem_u32(const void* p) {
    uint32_t a;
    asm("{ .reg .u64 t; cvta.to.shared.u64 t, %1; cvt.u32.u64 %0, t; }" : "=r"(a) : "l"(p));
    return a;
}
__device__ __forceinline__ void ldsm_x4_trans(uint32_t& r0, uint32_t& r1,
                                              uint32_t& r2, uint32_t& r3, uint32_t addr) {
    asm volatile("ldmatrix.sync.aligned.m8n8.x4.trans.shared.b16 {%0,%1,%2,%3}, [%4];"
                 : "=r"(r0), "=r"(r1), "=r"(r2), "=r"(r3) : "r"(addr));
}

// ---------------- kernel 0: zero accumulators ----------------
__global__ void k_zero() {
    int i = blockIdx.x * blockDim.x + threadIdx.x;
    if (i < B * K * C) g_sums_x[i] = 0.f;
    if (i < C * C)     g_G[i] = 0.f;
    if (i < B * K)     g_cnt[i] = 0.f;
}

// ---------------- kernel 0.5: prep w^T hi/lo ----------------
__global__ void k_wprep(const float* __restrict__ w) {
    int i = blockIdx.x * 256 + threadIdx.x;
    if (i < C * C) {
        int c = i >> 7, d = i & 127;
        float v = w[i];
        __nv_bfloat16 h = __float2bfloat16(v);
        g_wh[d * 132 + c] = h;
        g_wl[d * 132 + c] = __float2bfloat16(v - __bfloat162float(h));
    }
}

// ---------------- kernel MM: M = W @ W^T (input-only; launch slot #3) ----------------
__global__ void k_MM(const float* __restrict__ Wm) {
    __shared__ float wi[C];
    int i = blockIdx.x, t = threadIdx.x;
    wi[t] = Wm[i * C + t];
    __syncthreads();
    float acc = 0.f;
#pragma unroll 8
    for (int c = 0; c < C; c++) acc += wi[c] * Wm[t * C + c];
    g_M[i * C + t] = acc;
}

// ================= kernel 1: fused stats pass (G, segment sums, counts) =================
// grid 256 (8 b x 32 segs of 2048 pixels), 256 threads, 16 chunks of 128 pixels (R8 config)
#define P1_PITCH 132
#define P1_XH 0
#define P1_XL 33792
#define P1_OH 67584
#define P1_TOTAL 84480

__global__ __launch_bounds__(256, 1) void k_pass1(const float* __restrict__ x,
                                                  const int* __restrict__ idx) {
    extern __shared__ char smem[];
    __nv_bfloat16* Xh = (__nv_bfloat16*)(smem + P1_XH);
    __nv_bfloat16* Xl = (__nv_bfloat16*)(smem + P1_XL);
    __nv_bfloat16* OH = (__nv_bfloat16*)(smem + P1_OH);
    __shared__ int   sidx[128];
    __shared__ float hcnt[K];

    int tid = threadIdx.x;
    int b   = blockIdx.x >> 5;
    int seg = blockIdx.x & 31;
    int lane = tid & 31, wid = tid >> 5;
    int gid = lane >> 2, tig = lane & 3;
    int dbase  = (wid & 3) * 32;    // G m-tile (rows c1)
    int msbase = (wid & 3) * 16;    // S m-tile (rows k)
    int pbase  = (wid >> 2) * 64;   // n-half (cols c2 / c)

    if (tid < K) hcnt[tid] = 0.f;

    float Dg[2][8][4];
    float Ds[8][4];
#pragma unroll
    for (int mf = 0; mf < 2; mf++)
#pragma unroll
        for (int nf = 0; nf < 8; nf++)
#pragma unroll
            for (int q = 0; q < 4; q++) Dg[mf][nf][q] = 0.f;
#pragma unroll
    for (int nf = 0; nf < 8; nf++)
#pragma unroll
        for (int q = 0; q < 4; q++) Ds[nf][q] = 0.f;

    const float* xb = x + (size_t)b * C * HW + seg * 2048;
    const int*   ib = idx + b * HW + seg * 2048;

    for (int ch = 0; ch < 16; ch++) {
        __syncthreads();
        if (tid < 128) sidx[tid] = ib[ch * 128 + tid];
        for (int i = tid; i < 4224; i += 256) ((uint32_t*)OH)[i] = 0u;
        for (int e = tid; e < 4096; e += 256) {
            int row = e >> 5, p4 = (e & 31) * 4;
            float4 v = *(const float4*)(xb + (size_t)row * HW + ch * 128 + p4);
            __nv_bfloat162 h0 = __floats2bfloat162_rn(v.x, v.y);
            __nv_bfloat162 h1 = __floats2bfloat162_rn(v.z, v.w);
            float l0 = v.x - __bfloat162float(h0.x);
            float l1 = v.y - __bfloat162float(h0.y);
            float l2 = v.z - __bfloat162float(h1.x);
            float l3 = v.w - __bfloat162float(h1.y);
            __nv_bfloat162 g0 = __floats2bfloat162_rn(l0, l1);
            __nv_bfloat162 g1 = __floats2bfloat162_rn(l2, l3);
            *(__nv_bfloat162*)&Xh[row * P1_PITCH + p4]     = h0;
            *(__nv_bfloat162*)&Xh[row * P1_PITCH + p4 + 2] = h1;
            *(__nv_bfloat162*)&Xl[row * P1_PITCH + p4]     = g0;
            *(__nv_bfloat162*)&Xl[row * P1_PITCH + p4 + 2] = g1;
        }
        __syncthreads();
        if (tid < 128) {
            int k = sidx[tid];
            OH[k * P1_PITCH + tid] = __float2bfloat16(1.0f);
            atomicAdd(&hcnt[k], 1.f);
        }
        __syncthreads();

#pragma unroll
        for (int ks = 0; ks < 8; ks++) {
            int k0 = ks * 16;
            uint32_t bh[8][2], bl[8][2];
#pragma unroll
            for (int nf = 0; nf < 8; nf++) {
                int cn = pbase + nf * 8 + gid;
                bh[nf][0] = *(const uint32_t*)&Xh[cn * P1_PITCH + k0 + 2 * tig];
                bh[nf][1] = *(const uint32_t*)&Xh[cn * P1_PITCH + k0 + 8 + 2 * tig];
                bl[nf][0] = *(const uint32_t*)&Xl[cn * P1_PITCH + k0 + 2 * tig];
                bl[nf][1] = *(const uint32_t*)&Xl[cn * P1_PITCH + k0 + 8 + 2 * tig];
            }
            uint32_t ah[2][4];
#pragma unroll
            for (int mf = 0; mf < 2; mf++) {
                int r0 = dbase + mf * 16 + gid;
                ah[mf][0] = *(const uint32_t*)&Xh[r0 * P1_PITCH + k0 + 2 * tig];
                ah[mf][1] = *(const uint32_t*)&Xh[(r0 + 8) * P1_PITCH + k0 + 2 * tig];
                ah[mf][2] = *(const uint32_t*)&Xh[r0 * P1_PITCH + k0 + 8 + 2 * tig];
                ah[mf][3] = *(const uint32_t*)&Xh[(r0 + 8) * P1_PITCH + k0 + 8 + 2 * tig];
            }
            uint32_t ao[4];
            {
                int m0 = msbase + gid;
                ao[0] = *(const uint32_t*)&OH[m0 * P1_PITCH + k0 + 2 * tig];
                ao[1] = *(const uint32_t*)&OH[(m0 + 8) * P1_PITCH + k0 + 2 * tig];
                ao[2] = *(const uint32_t*)&OH[m0 * P1_PITCH + k0 + 8 + 2 * tig];
                ao[3] = *(const uint32_t*)&OH[(m0 + 8) * P1_PITCH + k0 + 8 + 2 * tig];
            }
#pragma unroll
            for (int mf = 0; mf < 2; mf++)
#pragma unroll
                for (int nf = 0; nf < 8; nf++)
                    MMA_BF16(Dg[mf][nf], ah[mf], bh[nf]);
#pragma unroll
            for (int nf = 0; nf < 8; nf++) {
                MMA_BF16(Ds[nf], ao, bh[nf]);
                MMA_BF16(Ds[nf], ao, bl[nf]);
            }
        }
    }

    // ---- flush partials ----
#pragma unroll
    for (int mf = 0; mf < 2; mf++)
#pragma unroll
        for (int nf = 0; nf < 8; nf++) {
            int r0 = dbase + mf * 16 + gid;
            int cn = pbase + nf * 8 + 2 * tig;
            atomicAdd(&g_G[r0 * C + cn],           Dg[mf][nf][0]);
            atomicAdd(&g_G[r0 * C + cn + 1],       Dg[mf][nf][1]);
            atomicAdd(&g_G[(r0 + 8) * C + cn],     Dg[mf][nf][2]);
            atomicAdd(&g_G[(r0 + 8) * C + cn + 1], Dg[mf][nf][3]);
        }
#pragma unroll
    for (int nf = 0; nf < 8; nf++) {
        int m0 = msbase + gid;
        int cn = pbase + nf * 8 + 2 * tig;
        atomicAdd(&g_sums_x[(b * K + m0) * C + cn],           Ds[nf][0]);
        atomicAdd(&g_sums_x[(b * K + m0) * C + cn + 1],       Ds[nf][1]);
        atomicAdd(&g_sums_x[(b * K + m0 + 8) * C + cn],       Ds[nf][2]);
        atomicAdd(&g_sums_x[(b * K + m0 + 8) * C + cn + 1],   Ds[nf][3]);
    }
    __syncthreads();
    if (tid < K) atomicAdd(&g_cnt[b * K + tid], hcnt[tid]);
}

// ---------------- kernel sm: sumsq (grid [0,128)) | means (grid [128,640)) ----------------
__global__ void k_sm(const float* __restrict__ w) {
    int blk = blockIdx.x;
    int t = threadIdx.x;
    if (blk < 128) {
        __shared__ float wcol[C];
        __shared__ float red[C];
        int d = blk;
        wcol[t] = w[t * C + d];
        __syncthreads();
        float acc = 0.f;
#pragma unroll 8
        for (int c2 = 0; c2 < C; c2++) acc += g_G[t * C + c2] * wcol[c2];
        red[t] = acc * wcol[t];
        __syncthreads();
        for (int s = 64; s > 0; s >>= 1) {
            if (t < s) red[t] += red[t + s];
            __syncthreads();
        }
        if (t == 0) g_sumsq[d] = red[0];
    } else {
        __shared__ float s[C];
        int bk = blk - 128;
        s[t] = g_sums_x[bk * C + t];
        __syncthreads();
        float cnt = g_cnt[bk];
        float denom = (cnt == 0.f) ? 1.f : cnt;
        float acc = 0.f;
#pragma unroll 8
        for (int c = 0; c < C; c++) acc += s[c] * w[c * C + t];
        g_means[bk * C + t] = acc / denom;
    }
}

// ---------------- kernel 5: Y[b,k,d] = means[b,k,:] @ M ----------------
__global__ void k_Y() {
    __shared__ float ms[C];
    int bk = blockIdx.x;
    int d = threadIdx.x;
    ms[d] = g_means[bk * C + d];
    __syncthreads();
    float acc = 0.f;
#pragma unroll 8
    for (int c = 0; c < C; c++) acc += ms[c] * g_M[c * C + d];
    g_Y[bk * C + d] = acc;
}

// ---------------- kernel 6: adjacency + adj_means ----------------
__global__ __launch_bounds__(256) void k_adj(const float* __restrict__ adj_mask) {
    __shared__ float msm[K][C + 1];
    __shared__ float gq[K];
    int b = blockIdx.x, tid = threadIdx.x;
    const float* mb = g_means + b * K * C;
    const float* yb = g_Y + b * K * C;

    for (int i = tid; i < K * C; i += 256) msm[i >> 7][i & 127] = mb[i];
    __syncthreads();

    if (tid < K) {
        float a = 0.f;
#pragma unroll 8
        for (int d = 0; d < C; d++) a += yb[tid * C + d] * msm[tid][d];
        gq[tid] = a;
    }
    __syncthreads();

    for (int i = tid; i < K * K; i += 256) {
        int p = i >> 6, q = i & 63;
        float dot = 0.f;
#pragma unroll 8
        for (int d = 0; d < C; d++) dot += yb[p * C + d] * msm[q][d];
        float quad = gq[p] + gq[q] - 2.f * dot;
        g_adj[b * K * K + i] = (p == q) ? 0.f : expf(-quad) * adj_mask[i];
    }
    __syncthreads();

    for (int i = tid; i < K * C; i += 256) {
        int p = i >> 7, d = i & 127;
        const float* arow = g_adj + b * K * K + p * K;
        float acc = 0.f;
#pragma unroll 8
        for (int q = 0; q < K; q++) acc += arow[q] * msm[q][d];
        g_adjm[b * K * C + i] = acc;
    }
}

// ---------------- kernel 7: BN statistics (analytic) ----------------
__global__ void k_bnstats(const float* __restrict__ gamma, const float* __restrict__ beta) {
    int d = threadIdx.x;
    float S1 = 0.f, S2 = 0.f;
    for (int bk = 0; bk < B * K; bk++) {
        float cnt = g_cnt[bk];
        float denom = (cnt == 0.f) ? 1.f : cnt;
        float m = g_means[bk * C + d];
        float am = g_adjm[bk * C + d];
        float sxw = m * denom;
        S1 += sxw + cnt * am;
        S2 += 2.f * am * sxw + cnt * am * am;
    }
    S2 += g_sumsq[d];
    float mu = S1 / NTOT;
    float var = S2 / NTOT - mu * mu;
    float s = gamma[d] * rsqrtf(var + BN_EPS);
    g_s[d] = s;
    g_t[d] = beta[d] - mu * s;
}

// ---------------- kernel 8: bias table bias[b][d][k] = s[d]*adjm[b][k][d] + t[d] ----------------
__global__ void k_bias() {
    int b = blockIdx.x;
    for (int i = threadIdx.x; i < C * K; i += 256) {
        int d = i >> 6, k = i & 63;
        g_bias[b * C * K + i] = fmaf(g_s[d], g_adjm[(b * K + k) * C + d], g_t[d]);
    }
}

// ================= kernel 9: fused GEMM + output (ldmatrix.trans path) =================
// out[b,d,p] = s[d] * (x @ weight)[b,d,p] + bias[b,d,idx[p]]
#define A_PITCH 132
#define X_PITCH 136
#define GSM2_AH 0
#define GSM2_AL 33792
#define GSM2_XH 67584
#define GSM2_XL 102400
#define GSM2_TOTAL 137216

__global__ __launch_bounds__(256, 1) void k_gemm_out(const float* __restrict__ x,
                                                     const int* __restrict__ idx,
                                                     float* __restrict__ out) {
    extern __shared__ char smem[];
    __nv_bfloat16* Ah = (__nv_bfloat16*)(smem + GSM2_AH);
    __nv_bfloat16* Al = (__nv_bfloat16*)(smem + GSM2_AL);
    __nv_bfloat16* Xh = (__nv_bfloat16*)(smem + GSM2_XH);
    __nv_bfloat16* Xl = (__nv_bfloat16*)(smem + GSM2_XL);
    float* estage = (float*)smem;                 // epilogue alias over Ah+Al (67584 B)
    float* bsm    = (float*)(smem + GSM2_XH);     // epilogue alias over Xh (32768 B used)
    __shared__ float ssm[C];
    __shared__ int   sidxp[128];

    int tid = threadIdx.x;
    int b = blockIdx.x >> 9;
    int p0 = (blockIdx.x & 511) << 7;
    const float* xb = x + (size_t)b * C * HW + p0;

    if (tid < 128) sidxp[tid] = idx[b * HW + p0 + tid];
    if (tid < C) ssm[tid] = g_s[tid];

    // ---- copy prepped W hi/lo ----
    {
        const uint32_t* wh32 = (const uint32_t*)g_wh;
        const uint32_t* wl32 = (const uint32_t*)g_wl;
        uint32_t* ah32 = (uint32_t*)Ah;
        uint32_t* al32 = (uint32_t*)Al;
        for (int i = tid; i < 8448; i += 256) { ah32[i] = wh32[i]; al32[i] = wl32[i]; }
    }
    // ---- convert x -> [c][p] bf16 hi/lo (coalesced both sides, no transpose) ----
    for (int e = tid; e < 4096; e += 256) {
        int row = e >> 5, p4 = (e & 31) * 4;
        float4 v = *(const float4*)(xb + (size_t)row * HW + p4);
        __nv_bfloat162 h0 = __floats2bfloat162_rn(v.x, v.y);
        __nv_bfloat162 h1 = __floats2bfloat162_rn(v.z, v.w);
        float l0 = v.x - __bfloat162float(h0.x);
        float l1 = v.y - __bfloat162float(h0.y);
        float l2 = v.z - __bfloat162float(h1.x);
        float l3 = v.w - __bfloat162float(h1.y);
        __nv_bfloat162 g0 = __floats2bfloat162_rn(l0, l1);
        __nv_bfloat162 g1 = __floats2bfloat162_rn(l2, l3);
        *(__nv_bfloat162*)&Xh[row * X_PITCH + p4]     = h0;
        *(__nv_bfloat162*)&Xh[row * X_PITCH + p4 + 2] = h1;
        *(__nv_bfloat162*)&Xl[row * X_PITCH + p4]     = g0;
        *(__nv_bfloat162*)&Xl[row * X_PITCH + p4 + 2] = g1;
    }
    __syncthreads();

    // ---- mainloop ----
    int lane = tid & 31, wid = tid >> 5;
    int gid = lane >> 2, tig = lane & 3;
    int dbase = (wid & 3) * 32;        // warp m-tile
    int pbase = (wid >> 2) * 64;       // warp n-tile

    uint32_t xh_base = smem_u32(Xh);
    uint32_t xl_base = smem_u32(Xl);
    int lm_off = ((lane & 7) + ((lane >> 3) & 1) * 8) * X_PITCH
               + pbase + ((lane >> 4) & 1) * 8;

    float D[2][8][4];
#pragma unroll
    for (int mf = 0; mf < 2; mf++)
#pragma unroll
        for (int nf = 0; nf < 8; nf++)
#pragma unroll
            for (int q = 0; q < 4; q++) D[mf][nf][q] = 0.f;

#pragma unroll
    for (int ks = 0; ks < 8; ks++) {
        int k0 = ks * 16;
        uint32_t ah[2][4], al[2][4];
#pragma unroll
        for (int mf = 0; mf < 2; mf++) {
            int r0 = dbase + mf * 16 + gid;
            ah[mf][0] = *(const uint32_t*)&Ah[r0 * A_PITCH + k0 + 2 * tig];
            ah[mf][1] = *(const uint32_t*)&Ah[(r0 + 8) * A_PITCH + k0 + 2 * tig];
            ah[mf][2] = *(const uint32_t*)&Ah[r0 * A_PITCH + k0 + 8 + 2 * tig];
            ah[mf][3] = *(const uint32_t*)&Ah[(r0 + 8) * A_PITCH + k0 + 8 + 2 * tig];
            al[mf][0] = *(const uint32_t*)&Al[r0 * A_PITCH + k0 + 2 * tig];
            al[mf][1] = *(const uint32_t*)&Al[(r0 + 8) * A_PITCH + k0 + 2 * tig];
            al[mf][2] = *(const uint32_t*)&Al[r0 * A_PITCH + k0 + 8 + 2 * tig];
            al[mf][3] = *(const uint32_t*)&Al[(r0 + 8) * A_PITCH + k0 + 8 + 2 * tig];
        }
        uint32_t bh[8][2], bl[8][2];
#pragma unroll
        for (int nfp = 0; nfp < 4; nfp++) {
            uint32_t aoff = (uint32_t)(k0 * X_PITCH + lm_off + nfp * 16) * 2;
            ldsm_x4_trans(bh[2 * nfp][0], bh[2 * nfp][1],
                          bh[2 * nfp + 1][0], bh[2 * nfp + 1][1], xh_base + aoff);
            ldsm_x4_trans(bl[2 * nfp][0], bl[2 * nfp][1],
                          bl[2 * nfp + 1][0], bl[2 * nfp + 1][1], xl_base + aoff);
        }
#pragma unroll
        for (int mf = 0; mf < 2; mf++)
#pragma unroll
            for (int nf = 0; nf < 8; nf++) {
                MMA_BF16(D[mf][nf], ah[mf], bh[nf]);
                MMA_BF16(D[mf][nf], ah[mf], bl[nf]);
                MMA_BF16(D[mf][nf], al[mf], bh[nf]);
            }
    }
    __syncthreads();   // all smem reads done; estage/bsm may alias

    // ---- epilogue: restage D; load precomputed bias (contiguous); transform + store ----
#pragma unroll
    for (int mf = 0; mf < 2; mf++)
#pragma unroll
        for (int nf = 0; nf < 8; nf++) {
            float* dd = D[mf][nf];
            int r0 = dbase + mf * 16 + gid;
            int cn = pbase + nf * 8 + 2 * tig;
            float2 v01; v01.x = dd[0]; v01.y = dd[1];
            float2 v23; v23.x = dd[2]; v23.y = dd[3];
            *(float2*)&estage[r0 * A_PITCH + cn] = v01;
            *(float2*)&estage[(r0 + 8) * A_PITCH + cn] = v23;
        }
    {
        const float4* gb = (const float4*)(g_bias + b * C * K);
        float4* bs4 = (float4*)bsm;
        for (int i = tid; i < 2048; i += 256) bs4[i] = gb[i];
    }
    __syncthreads();

    float* ob = out + (size_t)b * C * HW + p0;
#pragma unroll
    for (int i = 0; i < 16; i++) {
        int flat = i * 256 + tid;          // 4096 float4 total
        int row = flat >> 5, c4 = (flat & 31) * 4;
        float4 v = *(float4*)&estage[row * A_PITCH + c4];
        float s = ssm[row];
        const float* brow = bsm + row * 64;
        float4 r;
        r.x = fmaf(s, v.x, brow[sidxp[c4 + 0]]);
        r.y = fmaf(s, v.y, brow[sidxp[c4 + 1]]);
        r.z = fmaf(s, v.z, brow[sidxp[c4 + 2]]);
        r.w = fmaf(s, v.w, brow[sidxp[c4 + 3]]);
        *(float4*)(ob + (size_t)row * HW + c4) = r;
    }
}

// ---------------- launch (k_pass1 is launch #4 -> gets profiled) ----------------
extern "C" void kernel_launch(void* const* d_in, const int* in_sizes, int n_in,
                              void* d_out, int out_size) {
    const float* x        = (const float*)d_in[0];
    const int*   index    = (const int*)d_in[1];
    const float* weight   = (const float*)d_in[2];
    const float* Wm       = (const float*)d_in[3];
    const float* adj_mask = (const float*)d_in[4];
    const float* gamma    = (const float*)d_in[5];
    const float* beta     = (const float*)d_in[6];
    float* out = (float*)d_out;

    cudaFuncSetAttribute(k_pass1,    cudaFuncAttributeMaxDynamicSharedMemorySize, P1_TOTAL);
    cudaFuncSetAttribute(k_gemm_out, cudaFuncAttributeMaxDynamicSharedMemorySize, GSM2_TOTAL);

    k_zero<<<256, 256>>>();                       // 1
    k_wprep<<<64, 256>>>(weight);                 // 2
    k_MM<<<128, 128>>>(Wm);                       // 3 (independent of pass1)
    k_pass1<<<256, 256, P1_TOTAL>>>(x, index);    // 4  <-- profiled slot
    k_sm<<<640, 128>>>(weight);                   // 5
    k_Y<<<B * K, 128>>>();                        // 6
    k_adj<<<B, 256>>>(adj_mask);                  // 7
    k_bnstats<<<1, 128>>>(gamma, beta);           // 8
    k_bias<<<B, 256>>>();                         // 9
    k_gemm_out<<<4096, 256, GSM2_TOTAL>>>(x, index, out);  // 10
}

// round 12
// speedup vs baseline: 1.1063x; 1.1063x over previous
#include <cuda_runtime.h>
#include <cuda_bf16.h>
#include <cstdint>

#define B 8
#define C 128
#define HW 65536
#define K 64
#define NTOT 524288.0f
#define BN_EPS 1e-5f

// ---------------- scratch (device globals; no allocation allowed) ----------------
__device__ float g_G[C * C];                    // Gram matrix sum_p x x^T
__device__ float g_sums_x[B * K * C];           // segment sums of x
__device__ float g_cnt[B * K];                  // segment counts
__device__ float g_sumsq[C];                    // per-channel sum of xw^2
__device__ float g_means[B * K * C];
__device__ float g_M[C * C];                    // W @ W^T
__device__ float g_Y[B * K * C];                // means @ M
__device__ float g_adj[B * K * K];
__device__ float g_adjm[B * K * C];             // adj_nd @ means
__device__ float g_bias[B * C * K];             // [b][d][k] = s*adjm + t
__device__ float g_s[C];
__device__ float g_t[C];
__device__ __nv_bfloat16 g_wh[C * 132];         // w^T hi  [d][c], pitch 132
__device__ __nv_bfloat16 g_wl[C * 132];         // w^T lo

#define MMA_BF16(d, a, bb) \
    asm volatile("mma.sync.aligned.m16n8k16.row.col.f32.bf16.bf16.f32 " \
        "{%0,%1,%2,%3}, {%4,%5,%6,%7}, {%8,%9}, {%0,%1,%2,%3};" \
        : "+f"((d)[0]), "+f"((d)[1]), "+f"((d)[2]), "+f"((d)[3]) \
        : "r"((a)[0]), "r"((a)[1]), "r"((a)[2]), "r"((a)[3]), \
          "r"((bb)[0]), "r"((bb)[1]))

__device__ __forceinline__ uint32_t smem_u32(const void* p) {
    uint32_t a;
    asm("{ .reg .u64 t; cvta.to.shared.u64 t, %1; cvt.u32.u64 %0, t; }" : "=r"(a) : "l"(p));
    return a;
}
__device__ __forceinline__ void ldsm_x4_trans(uint32_t& r0, uint32_t& r1,
                                              uint32_t& r2, uint32_t& r3, uint32_t addr) {
    asm volatile("ldmatrix.sync.aligned.m8n8.x4.trans.shared.b16 {%0,%1,%2,%3}, [%4];"
                 : "=r"(r0), "=r"(r1), "=r"(r2), "=r"(r3) : "r"(addr));
}

// ---------------- kernel 0: zero accumulators ----------------
__global__ void k_zero() {
    int i = blockIdx.x * blockDim.x + threadIdx.x;
    if (i < B * K * C) g_sums_x[i] = 0.f;
    if (i < C * C)     g_G[i] = 0.f;
    if (i < B * K)     g_cnt[i] = 0.f;
}

// ---------------- kernel 0.5: prep w^T hi/lo ----------------
__global__ void k_wprep(const float* __restrict__ w) {
    int i = blockIdx.x * 256 + threadIdx.x;
    if (i < C * C) {
        int c = i >> 7, d = i & 127;
        float v = w[i];
        __nv_bfloat16 h = __float2bfloat16(v);
        g_wh[d * 132 + c] = h;
        g_wl[d * 132 + c] = __float2bfloat16(v - __bfloat162float(h));
    }
}

// ---------------- kernel MM: M = W @ W^T ----------------
__global__ void k_MM(const float* __restrict__ Wm) {
    __shared__ float wi[C];
    int i = blockIdx.x, t = threadIdx.x;
    wi[t] = Wm[i * C + t];
    __syncthreads();
    float acc = 0.f;
#pragma unroll 8
    for (int c = 0; c < C; c++) acc += wi[c] * Wm[t * C + c];
    g_M[i * C + t] = acc;
}

// ================= kernel 1: fused stats pass (G, segment sums, counts) =================
// grid 128 (8 b x 16 segs of 4096 px), 512 threads, 32 chunks of 128 pixels.
// 16 warps: Dg warp tile 32(c1) x 32(c2); Ds warp tile 16(k) x 32(c).
#define P1_PITCH 132
#define P1_XH 0
#define P1_XL 33792
#define P1_OH 67584
#define P1_TOTAL 84480

__global__ __launch_bounds__(512, 1) void k_pass1(const float* __restrict__ x,
                                                  const int* __restrict__ idx) {
    extern __shared__ char smem[];
    __nv_bfloat16* Xh = (__nv_bfloat16*)(smem + P1_XH);
    __nv_bfloat16* Xl = (__nv_bfloat16*)(smem + P1_XL);
    __nv_bfloat16* OH = (__nv_bfloat16*)(smem + P1_OH);
    __shared__ int   sidx[128];
    __shared__ float hcnt[K];

    int tid = threadIdx.x;
    int b   = blockIdx.x >> 4;
    int seg = blockIdx.x & 15;
    int lane = tid & 31, wid = tid >> 5;
    int gid = lane >> 2, tig = lane & 3;
    int dbase  = (wid & 3) * 32;     // G m-tile (rows c1)
    int msbase = (wid & 3) * 16;     // S m-tile (rows k)
    int pbase  = (wid >> 2) * 32;    // n-tile (cols c2 / c)

    if (tid < K) hcnt[tid] = 0.f;

    float Dg[2][4][4];
    float Ds[4][4];
#pragma unroll
    for (int mf = 0; mf < 2; mf++)
#pragma unroll
        for (int nf = 0; nf < 4; nf++)
#pragma unroll
            for (int q = 0; q < 4; q++) Dg[mf][nf][q] = 0.f;
#pragma unroll
    for (int nf = 0; nf < 4; nf++)
#pragma unroll
        for (int q = 0; q < 4; q++) Ds[nf][q] = 0.f;

    const float* xb = x + (size_t)b * C * HW + seg * 4096;
    const int*   ib = idx + b * HW + seg * 4096;

    for (int ch = 0; ch < 32; ch++) {
        __syncthreads();
        if (tid < 128) sidx[tid] = ib[ch * 128 + tid];
        for (int i = tid; i < 4224; i += 512) ((uint32_t*)OH)[i] = 0u;
        for (int e = tid; e < 4096; e += 512) {
            int row = e >> 5, p4 = (e & 31) * 4;
            float4 v = *(const float4*)(xb + (size_t)row * HW + ch * 128 + p4);
            __nv_bfloat162 h0 = __floats2bfloat162_rn(v.x, v.y);
            __nv_bfloat162 h1 = __floats2bfloat162_rn(v.z, v.w);
            float l0 = v.x - __bfloat162float(h0.x);
            float l1 = v.y - __bfloat162float(h0.y);
            float l2 = v.z - __bfloat162float(h1.x);
            float l3 = v.w - __bfloat162float(h1.y);
            __nv_bfloat162 g0 = __floats2bfloat162_rn(l0, l1);
            __nv_bfloat162 g1 = __floats2bfloat162_rn(l2, l3);
            *(__nv_bfloat162*)&Xh[row * P1_PITCH + p4]     = h0;
            *(__nv_bfloat162*)&Xh[row * P1_PITCH + p4 + 2] = h1;
            *(__nv_bfloat162*)&Xl[row * P1_PITCH + p4]     = g0;
            *(__nv_bfloat162*)&Xl[row * P1_PITCH + p4 + 2] = g1;
        }
        __syncthreads();
        if (tid < 128) {
            int k = sidx[tid];
            OH[k * P1_PITCH + tid] = __float2bfloat16(1.0f);
            atomicAdd(&hcnt[k], 1.f);
        }
        __syncthreads();

#pragma unroll
        for (int ks = 0; ks < 8; ks++) {
            int k0 = ks * 16;
            uint32_t bh[4][2], bl[4][2];
#pragma unroll
            for (int nf = 0; nf < 4; nf++) {
                int cn = pbase + nf * 8 + gid;
                bh[nf][0] = *(const uint32_t*)&Xh[cn * P1_PITCH + k0 + 2 * tig];
                bh[nf][1] = *(const uint32_t*)&Xh[cn * P1_PITCH + k0 + 8 + 2 * tig];
                bl[nf][0] = *(const uint32_t*)&Xl[cn * P1_PITCH + k0 + 2 * tig];
                bl[nf][1] = *(const uint32_t*)&Xl[cn * P1_PITCH + k0 + 8 + 2 * tig];
            }
            uint32_t ah[2][4];
#pragma unroll
            for (int mf = 0; mf < 2; mf++) {
                int r0 = dbase + mf * 16 + gid;
                ah[mf][0] = *(const uint32_t*)&Xh[r0 * P1_PITCH + k0 + 2 * tig];
                ah[mf][1] = *(const uint32_t*)&Xh[(r0 + 8) * P1_PITCH + k0 + 2 * tig];
                ah[mf][2] = *(const uint32_t*)&Xh[r0 * P1_PITCH + k0 + 8 + 2 * tig];
                ah[mf][3] = *(const uint32_t*)&Xh[(r0 + 8) * P1_PITCH + k0 + 8 + 2 * tig];
            }
            uint32_t ao[4];
            {
                int m0 = msbase + gid;
                ao[0] = *(const uint32_t*)&OH[m0 * P1_PITCH + k0 + 2 * tig];
                ao[1] = *(const uint32_t*)&OH[(m0 + 8) * P1_PITCH + k0 + 2 * tig];
                ao[2] = *(const uint32_t*)&OH[m0 * P1_PITCH + k0 + 8 + 2 * tig];
                ao[3] = *(const uint32_t*)&OH[(m0 + 8) * P1_PITCH + k0 + 8 + 2 * tig];
            }
#pragma unroll
            for (int mf = 0; mf < 2; mf++)
#pragma unroll
                for (int nf = 0; nf < 4; nf++)
                    MMA_BF16(Dg[mf][nf], ah[mf], bh[nf]);
#pragma unroll
            for (int nf = 0; nf < 4; nf++) {
                MMA_BF16(Ds[nf], ao, bh[nf]);
                MMA_BF16(Ds[nf], ao, bl[nf]);
            }
        }
    }

    // ---- flush partials ----
#pragma unroll
    for (int mf = 0; mf < 2; mf++)
#pragma unroll
        for (int nf = 0; nf < 4; nf++) {
            int r0 = dbase + mf * 16 + gid;
            int cn = pbase + nf * 8 + 2 * tig;
            atomicAdd(&g_G[r0 * C + cn],           Dg[mf][nf][0]);
            atomicAdd(&g_G[r0 * C + cn + 1],       Dg[mf][nf][1]);
            atomicAdd(&g_G[(r0 + 8) * C + cn],     Dg[mf][nf][2]);
            atomicAdd(&g_G[(r0 + 8) * C + cn + 1], Dg[mf][nf][3]);
        }
#pragma unroll
    for (int nf = 0; nf < 4; nf++) {
        int m0 = msbase + gid;
        int cn = pbase + nf * 8 + 2 * tig;
        atomicAdd(&g_sums_x[(b * K + m0) * C + cn],           Ds[nf][0]);
        atomicAdd(&g_sums_x[(b * K + m0) * C + cn + 1],       Ds[nf][1]);
        atomicAdd(&g_sums_x[(b * K + m0 + 8) * C + cn],       Ds[nf][2]);
        atomicAdd(&g_sums_x[(b * K + m0 + 8) * C + cn + 1],   Ds[nf][3]);
    }
    __syncthreads();
    if (tid < K) atomicAdd(&g_cnt[b * K + tid], hcnt[tid]);
}

// ---------------- kernel sm: sumsq (grid [0,128)) | means (grid [128,640)) ----------------
__global__ void k_sm(const float* __restrict__ w) {
    int blk = blockIdx.x;
    int t = threadIdx.x;
    if (blk < 128) {
        __shared__ float wcol[C];
        __shared__ float red[C];
        int d = blk;
        wcol[t] = w[t * C + d];
        __syncthreads();
        float acc = 0.f;
#pragma unroll 8
        for (int c2 = 0; c2 < C; c2++) acc += g_G[t * C + c2] * wcol[c2];
        red[t] = acc * wcol[t];
        __syncthreads();
        for (int s = 64; s > 0; s >>= 1) {
            if (t < s) red[t] += red[t + s];
            __syncthreads();
        }
        if (t == 0) g_sumsq[d] = red[0];
    } else {
        __shared__ float s[C];
        int bk = blk - 128;
        s[t] = g_sums_x[bk * C + t];
        __syncthreads();
        float cnt = g_cnt[bk];
        float denom = (cnt == 0.f) ? 1.f : cnt;
        float acc = 0.f;
#pragma unroll 8
        for (int c = 0; c < C; c++) acc += s[c] * w[c * C + t];
        g_means[bk * C + t] = acc / denom;
    }
}

// ---------------- kernel 5: Y[b,k,d] = means[b,k,:] @ M ----------------
__global__ void k_Y() {
    __shared__ float ms[C];
    int bk = blockIdx.x;
    int d = threadIdx.x;
    ms[d] = g_means[bk * C + d];
    __syncthreads();
    float acc = 0.f;
#pragma unroll 8
    for (int c = 0; c < C; c++) acc += ms[c] * g_M[c * C + d];
    g_Y[bk * C + d] = acc;
}

// ---------------- kernel 6: adjacency + adj_means ----------------
__global__ __launch_bounds__(256) void k_adj(const float* __restrict__ adj_mask) {
    __shared__ float msm[K][C + 1];
    __shared__ float gq[K];
    int b = blockIdx.x, tid = threadIdx.x;
    const float* mb = g_means + b * K * C;
    const float* yb = g_Y + b * K * C;

    for (int i = tid; i < K * C; i += 256) msm[i >> 7][i & 127] = mb[i];
    __syncthreads();

    if (tid < K) {
        float a = 0.f;
#pragma unroll 8
        for (int d = 0; d < C; d++) a += yb[tid * C + d] * msm[tid][d];
        gq[tid] = a;
    }
    __syncthreads();

    for (int i = tid; i < K * K; i += 256) {
        int p = i >> 6, q = i & 63;
        float dot = 0.f;
#pragma unroll 8
        for (int d = 0; d < C; d++) dot += yb[p * C + d] * msm[q][d];
        float quad = gq[p] + gq[q] - 2.f * dot;
        g_adj[b * K * K + i] = (p == q) ? 0.f : expf(-quad) * adj_mask[i];
    }
    __syncthreads();

    for (int i = tid; i < K * C; i += 256) {
        int p = i >> 7, d = i & 127;
        const float* arow = g_adj + b * K * K + p * K;
        float acc = 0.f;
#pragma unroll 8
        for (int q = 0; q < K; q++) acc += arow[q] * msm[q][d];
        g_adjm[b * K * C + i] = acc;
    }
}

// ---------------- kernel 7: BN statistics (analytic) ----------------
__global__ void k_bnstats(const float* __restrict__ gamma, const float* __restrict__ beta) {
    int d = threadIdx.x;
    float S1 = 0.f, S2 = 0.f;
    for (int bk = 0; bk < B * K; bk++) {
        float cnt = g_cnt[bk];
        float denom = (cnt == 0.f) ? 1.f : cnt;
        float m = g_means[bk * C + d];
        float am = g_adjm[bk * C + d];
        float sxw = m * denom;
        S1 += sxw + cnt * am;
        S2 += 2.f * am * sxw + cnt * am * am;
    }
    S2 += g_sumsq[d];
    float mu = S1 / NTOT;
    float var = S2 / NTOT - mu * mu;
    float s = gamma[d] * rsqrtf(var + BN_EPS);
    g_s[d] = s;
    g_t[d] = beta[d] - mu * s;
}

// ---------------- kernel 8: bias table bias[b][d][k] = s[d]*adjm[b][k][d] + t[d] ----------------
__global__ void k_bias() {
    int b = blockIdx.x;
    for (int i = threadIdx.x; i < C * K; i += 256) {
        int d = i >> 6, k = i & 63;
        g_bias[b * C * K + i] = fmaf(g_s[d], g_adjm[(b * K + k) * C + d], g_t[d]);
    }
}

// ================= kernel 9: fused GEMM + output (512 threads, ldmatrix.trans) =================
// out[b,d,p] = s[d] * (x @ weight)[b,d,p] + bias[b,d,idx[p]]
#define A_PITCH 132
#define X_PITCH 136
#define GSM2_AH 0
#define GSM2_AL 33792
#define GSM2_XH 67584
#define GSM2_XL 102400
#define GSM2_TOTAL 137216

__global__ __launch_bounds__(512, 1) void k_gemm_out(const float* __restrict__ x,
                                                     const int* __restrict__ idx,
                                                     float* __restrict__ out) {
    extern __shared__ char smem[];
    __nv_bfloat16* Ah = (__nv_bfloat16*)(smem + GSM2_AH);
    __nv_bfloat16* Al = (__nv_bfloat16*)(smem + GSM2_AL);
    __nv_bfloat16* Xh = (__nv_bfloat16*)(smem + GSM2_XH);
    __nv_bfloat16* Xl = (__nv_bfloat16*)(smem + GSM2_XL);
    float* estage = (float*)smem;                 // epilogue alias over Ah+Al (67584 B)
    float* bsm    = (float*)(smem + GSM2_XH);     // epilogue alias over Xh (32768 B used)
    __shared__ float ssm[C];
    __shared__ int   sidxp[128];

    int tid = threadIdx.x;
    int b = blockIdx.x >> 9;
    int p0 = (blockIdx.x & 511) << 7;
    const float* xb = x + (size_t)b * C * HW + p0;

    if (tid < 128) sidxp[tid] = idx[b * HW + p0 + tid];
    if (tid < C) ssm[tid] = g_s[tid];

    // ---- copy prepped W hi/lo ----
    {
        const uint32_t* wh32 = (const uint32_t*)g_wh;
        const uint32_t* wl32 = (const uint32_t*)g_wl;
        uint32_t* ah32 = (uint32_t*)Ah;
        uint32_t* al32 = (uint32_t*)Al;
        for (int i = tid; i < 8448; i += 512) { ah32[i] = wh32[i]; al32[i] = wl32[i]; }
    }
    // ---- convert x -> [c][p] bf16 hi/lo ----
    for (int e = tid; e < 4096; e += 512) {
        int row = e >> 5, p4 = (e & 31) * 4;
        float4 v = *(const float4*)(xb + (size_t)row * HW + p4);
        __nv_bfloat162 h0 = __floats2bfloat162_rn(v.x, v.y);
        __nv_bfloat162 h1 = __floats2bfloat162_rn(v.z, v.w);
        float l0 = v.x - __bfloat162float(h0.x);
        float l1 = v.y - __bfloat162float(h0.y);
        float l2 = v.z - __bfloat162float(h1.x);
        float l3 = v.w - __bfloat162float(h1.y);
        __nv_bfloat162 g0 = __floats2bfloat162_rn(l0, l1);
        __nv_bfloat162 g1 = __floats2bfloat162_rn(l2, l3);
        *(__nv_bfloat162*)&Xh[row * X_PITCH + p4]     = h0;
        *(__nv_bfloat162*)&Xh[row * X_PITCH + p4 + 2] = h1;
        *(__nv_bfloat162*)&Xl[row * X_PITCH + p4]     = g0;
        *(__nv_bfloat162*)&Xl[row * X_PITCH + p4 + 2] = g1;
    }
    __syncthreads();

    // ---- mainloop: 16 warps, warp tile 32(d) x 32(p) ----
    int lane = tid & 31, wid = tid >> 5;
    int gid = lane >> 2, tig = lane & 3;
    int dbase = (wid & 3) * 32;
    int pbase = (wid >> 2) * 32;

    uint32_t xh_base = smem_u32(Xh);
    uint32_t xl_base = smem_u32(Xl);
    int lm_off = ((lane & 7) + ((lane >> 3) & 1) * 8) * X_PITCH
               + pbase + ((lane >> 4) & 1) * 8;

    float D[2][4][4];
#pragma unroll
    for (int mf = 0; mf < 2; mf++)
#pragma unroll
        for (int nf = 0; nf < 4; nf++)
#pragma unroll
            for (int q = 0; q < 4; q++) D[mf][nf][q] = 0.f;

#pragma unroll
    for (int ks = 0; ks < 8; ks++) {
        int k0 = ks * 16;
        uint32_t ah[2][4], al[2][4];
#pragma unroll
        for (int mf = 0; mf < 2; mf++) {
            int r0 = dbase + mf * 16 + gid;
            ah[mf][0] = *(const uint32_t*)&Ah[r0 * A_PITCH + k0 + 2 * tig];
            ah[mf][1] = *(const uint32_t*)&Ah[(r0 + 8) * A_PITCH + k0 + 2 * tig];
            ah[mf][2] = *(const uint32_t*)&Ah[r0 * A_PITCH + k0 + 8 + 2 * tig];
            ah[mf][3] = *(const uint32_t*)&Ah[(r0 + 8) * A_PITCH + k0 + 8 + 2 * tig];
            al[mf][0] = *(const uint32_t*)&Al[r0 * A_PITCH + k0 + 2 * tig];
            al[mf][1] = *(const uint32_t*)&Al[(r0 + 8) * A_PITCH + k0 + 2 * tig];
            al[mf][2] = *(const uint32_t*)&Al[r0 * A_PITCH + k0 + 8 + 2 * tig];
            al[mf][3] = *(const uint32_t*)&Al[(r0 + 8) * A_PITCH + k0 + 8 + 2 * tig];
        }
        uint32_t bh[4][2], bl[4][2];
#pragma unroll
        for (int nfp = 0; nfp < 2; nfp++) {
            uint32_t aoff = (uint32_t)(k0 * X_PITCH + lm_off + nfp * 16) * 2;
            ldsm_x4_trans(bh[2 * nfp][0], bh[2 * nfp][1],
                          bh[2 * nfp + 1][0], bh[2 * nfp + 1][1], xh_base + aoff);
            ldsm_x4_trans(bl[2 * nfp][0], bl[2 * nfp][1],
                          bl[2 * nfp + 1][0], bl[2 * nfp + 1][1], xl_base + aoff);
        }
#pragma unroll
        for (int mf = 0; mf < 2; mf++)
#pragma unroll
            for (int nf = 0; nf < 4; nf++) {
                MMA_BF16(D[mf][nf], ah[mf], bh[nf]);
                MMA_BF16(D[mf][nf], ah[mf], bl[nf]);
                MMA_BF16(D[mf][nf], al[mf], bh[nf]);
            }
    }
    __syncthreads();   // all smem reads done; estage/bsm may alias

    // ---- epilogue: restage D; load precomputed bias (contiguous); transform + store ----
#pragma unroll
    for (int mf = 0; mf < 2; mf++)
#pragma unroll
        for (int nf = 0; nf < 4; nf++) {
            float* dd = D[mf][nf];
            int r0 = dbase + mf * 16 + gid;
            int cn = pbase + nf * 8 + 2 * tig;
            float2 v01; v01.x = dd[0]; v01.y = dd[1];
            float2 v23; v23.x = dd[2]; v23.y = dd[3];
            *(float2*)&estage[r0 * A_PITCH + cn] = v01;
            *(float2*)&estage[(r0 + 8) * A_PITCH + cn] = v23;
        }
    {
        const float4* gb = (const float4*)(g_bias + b * C * K);
        float4* bs4 = (float4*)bsm;
        for (int i = tid; i < 2048; i += 512) bs4[i] = gb[i];
    }
    __syncthreads();

    float* ob = out + (size_t)b * C * HW + p0;
#pragma unroll
    for (int i = 0; i < 8; i++) {
        int flat = i * 512 + tid;          // 4096 float4 total
        int row = flat >> 5, c4 = (flat & 31) * 4;
        float4 v = *(float4*)&estage[row * A_PITCH + c4];
        float s = ssm[row];
        const float* brow = bsm + row * 64;
        float4 r;
        r.x = fmaf(s, v.x, brow[sidxp[c4 + 0]]);
        r.y = fmaf(s, v.y, brow[sidxp[c4 + 1]]);
        r.z = fmaf(s, v.z, brow[sidxp[c4 + 2]]);
        r.w = fmaf(s, v.w, brow[sidxp[c4 + 3]]);
        *(float4*)(ob + (size_t)row * HW + c4) = r;
    }
}

// ---------------- launch (k_pass1 stays launch #4 -> profiled) ----------------
extern "C" void kernel_launch(void* const* d_in, const int* in_sizes, int n_in,
                              void* d_out, int out_size) {
    const float* x        = (const float*)d_in[0];
    const int*   index    = (const int*)d_in[1];
    const float* weight   = (const float*)d_in[2];
    const float* Wm       = (const float*)d_in[3];
    const float* adj_mask = (const float*)d_in[4];
    const float* gamma    = (const float*)d_in[5];
    const float* beta     = (const float*)d_in[6];
    float* out = (float*)d_out;

    cudaFuncSetAttribute(k_pass1,    cudaFuncAttributeMaxDynamicSharedMemorySize, P1_TOTAL);
    cudaFuncSetAttribute(k_gemm_out, cudaFuncAttributeMaxDynamicSharedMemorySize, GSM2_TOTAL);

    k_zero<<<256, 256>>>();                       // 1
    k_wprep<<<64, 256>>>(weight);                 // 2
    k_MM<<<128, 128>>>(Wm);                       // 3
    k_pass1<<<128, 512, P1_TOTAL>>>(x, index);    // 4  <-- profiled slot
    k_sm<<<640, 128>>>(weight);                   // 5
    k_Y<<<B * K, 128>>>();                        // 6
    k_adj<<<B, 256>>>(adj_mask);                  // 7
    k_bnstats<<<1, 128>>>(gamma, beta);           // 8
    k_bias<<<B, 256>>>();                         // 9
    k_gemm_out<<<4096, 512, GSM2_TOTAL>>>(x, index, out);  // 10
}

// round 13
// speedup vs baseline: 1.3349x; 1.2066x over previous
#include <cuda_runtime.h>
#include <cuda_bf16.h>
#include <cstdint>

#define B 8
#define C 128
#define HW 65536
#define K 64
#define NTOT 524288.0f
#define BN_EPS 1e-5f

// ---------------- scratch (device globals; no allocation allowed) ----------------
__device__ float g_G[C * C];                    // Gram matrix sum_p x x^T
__device__ float g_sums_x[B * K * C];           // segment sums of x
__device__ float g_cnt[B * K];                  // segment counts
__device__ float g_sumsq[C];                    // per-channel sum of xw^2
__device__ float g_means[B * K * C];
__device__ float g_M[C * C];                    // W @ W^T
__device__ float g_Y[B * K * C];                // means @ M
__device__ float g_adj[B * K * K];
__device__ float g_adjm[B * K * C];             // adj_nd @ means
__device__ float g_bias[B * C * K];             // [b][d][k] = s*adjm + t
__device__ float g_s[C];
__device__ float g_t[C];
__device__ __nv_bfloat16 g_wh[C * 132];         // w^T hi  [d][c], pitch 132
__device__ __nv_bfloat16 g_wl[C * 132];         // w^T lo

#define MMA_BF16(d, a, bb) \
    asm volatile("mma.sync.aligned.m16n8k16.row.col.f32.bf16.bf16.f32 " \
        "{%0,%1,%2,%3}, {%4,%5,%6,%7}, {%8,%9}, {%0,%1,%2,%3};" \
        : "+f"((d)[0]), "+f"((d)[1]), "+f"((d)[2]), "+f"((d)[3]) \
        : "r"((a)[0]), "r"((a)[1]), "r"((a)[2]), "r"((a)[3]), \
          "r"((bb)[0]), "r"((bb)[1]))

__device__ __forceinline__ uint32_t smem_u32(const void* p) {
    uint32_t a;
    asm("{ .reg .u64 t; cvta.to.shared.u64 t, %1; cvt.u32.u64 %0, t; }" : "=r"(a) : "l"(p));
    return a;
}
__device__ __forceinline__ void ldsm_x4_trans(uint32_t& r0, uint32_t& r1,
                                              uint32_t& r2, uint32_t& r3, uint32_t addr) {
    asm volatile("ldmatrix.sync.aligned.m8n8.x4.trans.shared.b16 {%0,%1,%2,%3}, [%4];"
                 : "=r"(r0), "=r"(r1), "=r"(r2), "=r"(r3) : "r"(addr));
}

// ---------------- kernel 0: zero accumulators ----------------
__global__ void k_zero() {
    int i = blockIdx.x * blockDim.x + threadIdx.x;
    if (i < B * K * C) g_sums_x[i] = 0.f;
    if (i < C * C)     g_G[i] = 0.f;
    if (i < B * K)     g_cnt[i] = 0.f;
}

// ---------------- kernel 0.5: prep w^T hi/lo ----------------
__global__ void k_wprep(const float* __restrict__ w) {
    int i = blockIdx.x * 256 + threadIdx.x;
    if (i < C * C) {
        int c = i >> 7, d = i & 127;
        float v = w[i];
        __nv_bfloat16 h = __float2bfloat16(v);
        g_wh[d * 132 + c] = h;
        g_wl[d * 132 + c] = __float2bfloat16(v - __bfloat162float(h));
    }
}

// ---------------- kernel MM: M = W @ W^T ----------------
__global__ void k_MM(const float* __restrict__ Wm) {
    __shared__ float wi[C];
    int i = blockIdx.x, t = threadIdx.x;
    wi[t] = Wm[i * C + t];
    __syncthreads();
    float acc = 0.f;
#pragma unroll 8
    for (int c = 0; c < C; c++) acc += wi[c] * Wm[t * C + c];
    g_M[i * C + t] = acc;
}

// ================= kernel 1: fused stats pass (G, segment sums, counts) =================
// grid 128 (8 b x 16 segs of 4096 px), 512 threads, 32 chunks of 128 pixels.
#define P1_PITCH 132
#define P1_XH 0
#define P1_XL 33792
#define P1_OH 67584
#define P1_TOTAL 84480

__global__ __launch_bounds__(512, 1) void k_pass1(const float* __restrict__ x,
                                                  const int* __restrict__ idx) {
    extern __shared__ char smem[];
    __nv_bfloat16* Xh = (__nv_bfloat16*)(smem + P1_XH);
    __nv_bfloat16* Xl = (__nv_bfloat16*)(smem + P1_XL);
    __nv_bfloat16* OH = (__nv_bfloat16*)(smem + P1_OH);
    __shared__ int   sidx[128];
    __shared__ float hcnt[K];

    int tid = threadIdx.x;
    int b   = blockIdx.x >> 4;
    int seg = blockIdx.x & 15;
    int lane = tid & 31, wid = tid >> 5;
    int gid = lane >> 2, tig = lane & 3;
    int dbase  = (wid & 3) * 32;     // G m-tile (rows c1)
    int msbase = (wid & 3) * 16;     // S m-tile (rows k)
    int pbase  = (wid >> 2) * 32;    // n-tile (cols c2 / c)

    if (tid < K) hcnt[tid] = 0.f;

    float Dg[2][4][4];
    float Ds[4][4];
#pragma unroll
    for (int mf = 0; mf < 2; mf++)
#pragma unroll
        for (int nf = 0; nf < 4; nf++)
#pragma unroll
            for (int q = 0; q < 4; q++) Dg[mf][nf][q] = 0.f;
#pragma unroll
    for (int nf = 0; nf < 4; nf++)
#pragma unroll
        for (int q = 0; q < 4; q++) Ds[nf][q] = 0.f;

    const float* xb = x + (size_t)b * C * HW + seg * 4096;
    const int*   ib = idx + b * HW + seg * 4096;

    for (int ch = 0; ch < 32; ch++) {
        __syncthreads();
        if (tid < 128) sidx[tid] = ib[ch * 128 + tid];
        for (int i = tid; i < 4224; i += 512) ((uint32_t*)OH)[i] = 0u;
        for (int e = tid; e < 4096; e += 512) {
            int row = e >> 5, p4 = (e & 31) * 4;
            float4 v = *(const float4*)(xb + (size_t)row * HW + ch * 128 + p4);
            __nv_bfloat162 h0 = __floats2bfloat162_rn(v.x, v.y);
            __nv_bfloat162 h1 = __floats2bfloat162_rn(v.z, v.w);
            float l0 = v.x - __bfloat162float(h0.x);
            float l1 = v.y - __bfloat162float(h0.y);
            float l2 = v.z - __bfloat162float(h1.x);
            float l3 = v.w - __bfloat162float(h1.y);
            __nv_bfloat162 g0 = __floats2bfloat162_rn(l0, l1);
            __nv_bfloat162 g1 = __floats2bfloat162_rn(l2, l3);
            *(__nv_bfloat162*)&Xh[row * P1_PITCH + p4]     = h0;
            *(__nv_bfloat162*)&Xh[row * P1_PITCH + p4 + 2] = h1;
            *(__nv_bfloat162*)&Xl[row * P1_PITCH + p4]     = g0;
            *(__nv_bfloat162*)&Xl[row * P1_PITCH + p4 + 2] = g1;
        }
        __syncthreads();
        if (tid < 128) {
            int k = sidx[tid];
            OH[k * P1_PITCH + tid] = __float2bfloat16(1.0f);
            atomicAdd(&hcnt[k], 1.f);
        }
        __syncthreads();

#pragma unroll
        for (int ks = 0; ks < 8; ks++) {
            int k0 = ks * 16;
            uint32_t bh[4][2], bl[4][2];
#pragma unroll
            for (int nf = 0; nf < 4; nf++) {
                int cn = pbase + nf * 8 + gid;
                bh[nf][0] = *(const uint32_t*)&Xh[cn * P1_PITCH + k0 + 2 * tig];
                bh[nf][1] = *(const uint32_t*)&Xh[cn * P1_PITCH + k0 + 8 + 2 * tig];
                bl[nf][0] = *(const uint32_t*)&Xl[cn * P1_PITCH + k0 + 2 * tig];
                bl[nf][1] = *(const uint32_t*)&Xl[cn * P1_PITCH + k0 + 8 + 2 * tig];
            }
            uint32_t ah[2][4];
#pragma unroll
            for (int mf = 0; mf < 2; mf++) {
                int r0 = dbase + mf * 16 + gid;
                ah[mf][0] = *(const uint32_t*)&Xh[r0 * P1_PITCH + k0 + 2 * tig];
                ah[mf][1] = *(const uint32_t*)&Xh[(r0 + 8) * P1_PITCH + k0 + 2 * tig];
                ah[mf][2] = *(const uint32_t*)&Xh[r0 * P1_PITCH + k0 + 8 + 2 * tig];
                ah[mf][3] = *(const uint32_t*)&Xh[(r0 + 8) * P1_PITCH + k0 + 8 + 2 * tig];
            }
            uint32_t ao[4];
            {
                int m0 = msbase + gid;
                ao[0] = *(const uint32_t*)&OH[m0 * P1_PITCH + k0 + 2 * tig];
                ao[1] = *(const uint32_t*)&OH[(m0 + 8) * P1_PITCH + k0 + 2 * tig];
                ao[2] = *(const uint32_t*)&OH[m0 * P1_PITCH + k0 + 8 + 2 * tig];
                ao[3] = *(const uint32_t*)&OH[(m0 + 8) * P1_PITCH + k0 + 8 + 2 * tig];
            }
#pragma unroll
            for (int mf = 0; mf < 2; mf++)
#pragma unroll
                for (int nf = 0; nf < 4; nf++)
                    MMA_BF16(Dg[mf][nf], ah[mf], bh[nf]);
#pragma unroll
            for (int nf = 0; nf < 4; nf++) {
                MMA_BF16(Ds[nf], ao, bh[nf]);
                MMA_BF16(Ds[nf], ao, bl[nf]);
            }
        }
    }

    // ---- flush partials ----
#pragma unroll
    for (int mf = 0; mf < 2; mf++)
#pragma unroll
        for (int nf = 0; nf < 4; nf++) {
            int r0 = dbase + mf * 16 + gid;
            int cn = pbase + nf * 8 + 2 * tig;
            atomicAdd(&g_G[r0 * C + cn],           Dg[mf][nf][0]);
            atomicAdd(&g_G[r0 * C + cn + 1],       Dg[mf][nf][1]);
            atomicAdd(&g_G[(r0 + 8) * C + cn],     Dg[mf][nf][2]);
            atomicAdd(&g_G[(r0 + 8) * C + cn + 1], Dg[mf][nf][3]);
        }
#pragma unroll
    for (int nf = 0; nf < 4; nf++) {
        int m0 = msbase + gid;
        int cn = pbase + nf * 8 + 2 * tig;
        atomicAdd(&g_sums_x[(b * K + m0) * C + cn],           Ds[nf][0]);
        atomicAdd(&g_sums_x[(b * K + m0) * C + cn + 1],       Ds[nf][1]);
        atomicAdd(&g_sums_x[(b * K + m0 + 8) * C + cn],       Ds[nf][2]);
        atomicAdd(&g_sums_x[(b * K + m0 + 8) * C + cn + 1],   Ds[nf][3]);
    }
    __syncthreads();
    if (tid < K) atomicAdd(&g_cnt[b * K + tid], hcnt[tid]);
}

// ---------------- kernel sm: sumsq (grid [0,128)) | means (grid [128,640)) ----------------
__global__ void k_sm(const float* __restrict__ w) {
    int blk = blockIdx.x;
    int t = threadIdx.x;
    if (blk < 128) {
        __shared__ float wcol[C];
        __shared__ float red[C];
        int d = blk;
        wcol[t] = w[t * C + d];
        __syncthreads();
        float acc = 0.f;
#pragma unroll 8
        for (int c2 = 0; c2 < C; c2++) acc += g_G[t * C + c2] * wcol[c2];
        red[t] = acc * wcol[t];
        __syncthreads();
        for (int s = 64; s > 0; s >>= 1) {
            if (t < s) red[t] += red[t + s];
            __syncthreads();
        }
        if (t == 0) g_sumsq[d] = red[0];
    } else {
        __shared__ float s[C];
        int bk = blk - 128;
        s[t] = g_sums_x[bk * C + t];
        __syncthreads();
        float cnt = g_cnt[bk];
        float denom = (cnt == 0.f) ? 1.f : cnt;
        float acc = 0.f;
#pragma unroll 8
        for (int c = 0; c < C; c++) acc += s[c] * w[c * C + t];
        g_means[bk * C + t] = acc / denom;
    }
}

// ---------------- kernel 5: Y[b,k,d] = means[b,k,:] @ M ----------------
__global__ void k_Y() {
    __shared__ float ms[C];
    int bk = blockIdx.x;
    int d = threadIdx.x;
    ms[d] = g_means[bk * C + d];
    __syncthreads();
    float acc = 0.f;
#pragma unroll 8
    for (int c = 0; c < C; c++) acc += ms[c] * g_M[c * C + d];
    g_Y[bk * C + d] = acc;
}

// ---------------- kernel 6: adjacency + adj_means ----------------
__global__ __launch_bounds__(256) void k_adj(const float* __restrict__ adj_mask) {
    __shared__ float msm[K][C + 1];
    __shared__ float gq[K];
    int b = blockIdx.x, tid = threadIdx.x;
    const float* mb = g_means + b * K * C;
    const float* yb = g_Y + b * K * C;

    for (int i = tid; i < K * C; i += 256) msm[i >> 7][i & 127] = mb[i];
    __syncthreads();

    if (tid < K) {
        float a = 0.f;
#pragma unroll 8
        for (int d = 0; d < C; d++) a += yb[tid * C + d] * msm[tid][d];
        gq[tid] = a;
    }
    __syncthreads();

    for (int i = tid; i < K * K; i += 256) {
        int p = i >> 6, q = i & 63;
        float dot = 0.f;
#pragma unroll 8
        for (int d = 0; d < C; d++) dot += yb[p * C + d] * msm[q][d];
        float quad = gq[p] + gq[q] - 2.f * dot;
        g_adj[b * K * K + i] = (p == q) ? 0.f : expf(-quad) * adj_mask[i];
    }
    __syncthreads();

    for (int i = tid; i < K * C; i += 256) {
        int p = i >> 7, d = i & 127;
        const float* arow = g_adj + b * K * K + p * K;
        float acc = 0.f;
#pragma unroll 8
        for (int q = 0; q < K; q++) acc += arow[q] * msm[q][d];
        g_adjm[b * K * C + i] = acc;
    }
}

// ---------------- kernel 7: BN statistics (analytic) ----------------
__global__ void k_bnstats(const float* __restrict__ gamma, const float* __restrict__ beta) {
    int d = threadIdx.x;
    float S1 = 0.f, S2 = 0.f;
    for (int bk = 0; bk < B * K; bk++) {
        float cnt = g_cnt[bk];
        float denom = (cnt == 0.f) ? 1.f : cnt;
        float m = g_means[bk * C + d];
        float am = g_adjm[bk * C + d];
        float sxw = m * denom;
        S1 += sxw + cnt * am;
        S2 += 2.f * am * sxw + cnt * am * am;
    }
    S2 += g_sumsq[d];
    float mu = S1 / NTOT;
    float var = S2 / NTOT - mu * mu;
    float s = gamma[d] * rsqrtf(var + BN_EPS);
    g_s[d] = s;
    g_t[d] = beta[d] - mu * s;
}

// ---------------- kernel 8: bias table bias[b][d][k] = s[d]*adjm[b][k][d] + t[d] ----------------
__global__ void k_bias() {
    int b = blockIdx.x;
    for (int i = threadIdx.x; i < C * K; i += 256) {
        int d = i >> 6, k = i & 63;
        g_bias[b * C * K + i] = fmaf(g_s[d], g_adjm[(b * K + k) * C + d], g_t[d]);
    }
}

// ================= kernel 9: persistent fused GEMM + output =================
// grid 128 (8 b x 16 segs of 4096 px), 512 threads, 32 chunks of 128 pixels.
// W hi/lo + bias table loaded ONCE per block; per chunk: convert -> mma -> store.
#define A_PITCH 132
#define X_PITCH 136
#define GO_AH 0
#define GO_AL 33792
#define GO_XH 67584
#define GO_XL 102400
#define GO_BIAS 137216
#define GO_TOTAL 169984

__global__ __launch_bounds__(512, 1) void k_gemm_out(const float* __restrict__ x,
                                                     const int* __restrict__ idx,
                                                     float* __restrict__ out) {
    extern __shared__ char smem[];
    __nv_bfloat16* Ah = (__nv_bfloat16*)(smem + GO_AH);
    __nv_bfloat16* Al = (__nv_bfloat16*)(smem + GO_AL);
    __nv_bfloat16* Xh = (__nv_bfloat16*)(smem + GO_XH);
    __nv_bfloat16* Xl = (__nv_bfloat16*)(smem + GO_XL);
    float* bsm    = (float*)(smem + GO_BIAS);     // persistent bias table (32 KB)
    float* estage = (float*)(smem + GO_XH);       // per-chunk epilogue alias over Xh/Xl
    __shared__ float ssm[C];
    __shared__ int   sidxp[128];

    int tid = threadIdx.x;
    int b   = blockIdx.x >> 4;
    int seg = blockIdx.x & 15;
    const float* xb = x + (size_t)b * C * HW + seg * 4096;
    const int*   ib = idx + b * HW + seg * 4096;
    float* ob = out + (size_t)b * C * HW + seg * 4096;

    if (tid < C) ssm[tid] = g_s[tid];

    // ---- one-time: W hi/lo + bias table ----
    {
        const uint32_t* wh32 = (const uint32_t*)g_wh;
        const uint32_t* wl32 = (const uint32_t*)g_wl;
        uint32_t* ah32 = (uint32_t*)Ah;
        uint32_t* al32 = (uint32_t*)Al;
        for (int i = tid; i < 8448; i += 512) { ah32[i] = wh32[i]; al32[i] = wl32[i]; }
        const float4* gb = (const float4*)(g_bias + b * C * K);
        float4* bs4 = (float4*)bsm;
        for (int i = tid; i < 2048; i += 512) bs4[i] = gb[i];
    }

    int lane = tid & 31, wid = tid >> 5;
    int gid = lane >> 2, tig = lane & 3;
    int dbase = (wid & 3) * 32;
    int pbase = (wid >> 2) * 32;

    uint32_t xh_base = smem_u32(Xh);
    uint32_t xl_base = smem_u32(Xl);
    int lm_off = ((lane & 7) + ((lane >> 3) & 1) * 8) * X_PITCH
               + pbase + ((lane >> 4) & 1) * 8;

    for (int ch = 0; ch < 32; ch++) {
        __syncthreads();    // estage/bsm-read of previous chunk done; Xh/Xl writable
        if (tid < 128) sidxp[tid] = ib[ch * 128 + tid];
        for (int e = tid; e < 4096; e += 512) {
            int row = e >> 5, p4 = (e & 31) * 4;
            float4 v = *(const float4*)(xb + (size_t)row * HW + ch * 128 + p4);
            __nv_bfloat162 h0 = __floats2bfloat162_rn(v.x, v.y);
            __nv_bfloat162 h1 = __floats2bfloat162_rn(v.z, v.w);
            float l0 = v.x - __bfloat162float(h0.x);
            float l1 = v.y - __bfloat162float(h0.y);
            float l2 = v.z - __bfloat162float(h1.x);
            float l3 = v.w - __bfloat162float(h1.y);
            __nv_bfloat162 g0 = __floats2bfloat162_rn(l0, l1);
            __nv_bfloat162 g1 = __floats2bfloat162_rn(l2, l3);
            *(__nv_bfloat162*)&Xh[row * X_PITCH + p4]     = h0;
            *(__nv_bfloat162*)&Xh[row * X_PITCH + p4 + 2] = h1;
            *(__nv_bfloat162*)&Xl[row * X_PITCH + p4]     = g0;
            *(__nv_bfloat162*)&Xl[row * X_PITCH + p4 + 2] = g1;
        }
        __syncthreads();

        float D[2][4][4];
#pragma unroll
        for (int mf = 0; mf < 2; mf++)
#pragma unroll
            for (int nf = 0; nf < 4; nf++)
#pragma unroll
                for (int q = 0; q < 4; q++) D[mf][nf][q] = 0.f;

#pragma unroll
        for (int ks = 0; ks < 8; ks++) {
            int k0 = ks * 16;
            uint32_t ah[2][4], al[2][4];
#pragma unroll
            for (int mf = 0; mf < 2; mf++) {
                int r0 = dbase + mf * 16 + gid;
                ah[mf][0] = *(const uint32_t*)&Ah[r0 * A_PITCH + k0 + 2 * tig];
                ah[mf][1] = *(const uint32_t*)&Ah[(r0 + 8) * A_PITCH + k0 + 2 * tig];
                ah[mf][2] = *(const uint32_t*)&Ah[r0 * A_PITCH + k0 + 8 + 2 * tig];
                ah[mf][3] = *(const uint32_t*)&Ah[(r0 + 8) * A_PITCH + k0 + 8 + 2 * tig];
                al[mf][0] = *(const uint32_t*)&Al[r0 * A_PITCH + k0 + 2 * tig];
                al[mf][1] = *(const uint32_t*)&Al[(r0 + 8) * A_PITCH + k0 + 2 * tig];
                al[mf][2] = *(const uint32_t*)&Al[r0 * A_PITCH + k0 + 8 + 2 * tig];
                al[mf][3] = *(const uint32_t*)&Al[(r0 + 8) * A_PITCH + k0 + 8 + 2 * tig];
            }
            uint32_t bh[4][2], bl[4][2];
#pragma unroll
            for (int nfp = 0; nfp < 2; nfp++) {
                uint32_t aoff = (uint32_t)(k0 * X_PITCH + lm_off + nfp * 16) * 2;
                ldsm_x4_trans(bh[2 * nfp][0], bh[2 * nfp][1],
                              bh[2 * nfp + 1][0], bh[2 * nfp + 1][1], xh_base + aoff);
                ldsm_x4_trans(bl[2 * nfp][0], bl[2 * nfp][1],
                              bl[2 * nfp + 1][0], bl[2 * nfp + 1][1], xl_base + aoff);
            }
#pragma unroll
            for (int mf = 0; mf < 2; mf++)
#pragma unroll
                for (int nf = 0; nf < 4; nf++) {
                    MMA_BF16(D[mf][nf], ah[mf], bh[nf]);
                    MMA_BF16(D[mf][nf], ah[mf], bl[nf]);
                    MMA_BF16(D[mf][nf], al[mf], bh[nf]);
                }
        }
        __syncthreads();    // Xh/Xl reads done; estage may overwrite

        // ---- epilogue: restage D (aliases Xh/Xl); transform + store ----
#pragma unroll
        for (int mf = 0; mf < 2; mf++)
#pragma unroll
            for (int nf = 0; nf < 4; nf++) {
                float* dd = D[mf][nf];
                int r0 = dbase + mf * 16 + gid;
                int cn = pbase + nf * 8 + 2 * tig;
                float2 v01; v01.x = dd[0]; v01.y = dd[1];
                float2 v23; v23.x = dd[2]; v23.y = dd[3];
                *(float2*)&estage[r0 * A_PITCH + cn] = v01;
                *(float2*)&estage[(r0 + 8) * A_PITCH + cn] = v23;
            }
        __syncthreads();

#pragma unroll
        for (int i = 0; i < 8; i++) {
            int flat = i * 512 + tid;          // 4096 float4 total
            int row = flat >> 5, c4 = (flat & 31) * 4;
            float4 v = *(float4*)&estage[row * A_PITCH + c4];
            float s = ssm[row];
            const float* brow = bsm + row * 64;
            float4 r;
            r.x = fmaf(s, v.x, brow[sidxp[c4 + 0]]);
            r.y = fmaf(s, v.y, brow[sidxp[c4 + 1]]);
            r.z = fmaf(s, v.z, brow[sidxp[c4 + 2]]);
            r.w = fmaf(s, v.w, brow[sidxp[c4 + 3]]);
            *(float4*)(ob + (size_t)row * HW + ch * 128 + c4) = r;
        }
    }
}

// ---------------- launch (k_pass1 stays launch #4 -> profiled) ----------------
extern "C" void kernel_launch(void* const* d_in, const int* in_sizes, int n_in,
                              void* d_out, int out_size) {
    const float* x        = (const float*)d_in[0];
    const int*   index    = (const int*)d_in[1];
    const float* weight   = (const float*)d_in[2];
    const float* Wm       = (const float*)d_in[3];
    const float* adj_mask = (const float*)d_in[4];
    const float* gamma    = (const float*)d_in[5];
    const float* beta     = (const float*)d_in[6];
    float* out = (float*)d_out;

    cudaFuncSetAttribute(k_pass1,    cudaFuncAttributeMaxDynamicSharedMemorySize, P1_TOTAL);
    cudaFuncSetAttribute(k_gemm_out, cudaFuncAttributeMaxDynamicSharedMemorySize, GO_TOTAL);

    k_zero<<<256, 256>>>();                       // 1
    k_wprep<<<64, 256>>>(weight);                 // 2
    k_MM<<<128, 128>>>(Wm);                       // 3
    k_pass1<<<128, 512, P1_TOTAL>>>(x, index);    // 4  <-- profiled slot
    k_sm<<<640, 128>>>(weight);                   // 5
    k_Y<<<B * K, 128>>>();                        // 6
    k_adj<<<B, 256>>>(adj_mask);                  // 7
    k_bnstats<<<1, 128>>>(gamma, beta);           // 8
    k_bias<<<B, 256>>>();                         // 9
    k_gemm_out<<<128, 512, GO_TOTAL>>>(x, index, out);  // 10
}

// round 14
// speedup vs baseline: 1.4124x; 1.0580x over previous
#include <cuda_runtime.h>
#include <cuda_bf16.h>
#include <cstdint>

#define B 8
#define C 128
#define HW 65536
#define K 64
#define NTOT 524288.0f
#define BN_EPS 1e-5f

// ---------------- scratch (device globals; no allocation allowed) ----------------
__device__ float g_G[C * C];                    // Gram matrix sum_p x x^T
__device__ float g_sums_x[B * K * C];           // segment sums of x
__device__ float g_cnt[B * K];                  // segment counts
__device__ float g_sumsq[C];                    // per-channel sum of xw^2
__device__ float g_means[B * K * C];
__device__ float g_M[C * C];                    // W @ W^T
__device__ float g_Y[B * K * C];                // means @ M
__device__ float g_adj[B * K * K];
__device__ float g_adjm[B * K * C];             // adj_nd @ means
__device__ float g_bias[B * C * K];             // [b][d][k] = s*adjm + t
__device__ float g_s[C];
__device__ float g_t[C];
__device__ __nv_bfloat16 g_wh[C * 136];         // w^T hi  [d][c], pitch 136
__device__ __nv_bfloat16 g_wl[C * 136];         // w^T lo

#define MMA_BF16(d, a, bb) \
    asm volatile("mma.sync.aligned.m16n8k16.row.col.f32.bf16.bf16.f32 " \
        "{%0,%1,%2,%3}, {%4,%5,%6,%7}, {%8,%9}, {%0,%1,%2,%3};" \
        : "+f"((d)[0]), "+f"((d)[1]), "+f"((d)[2]), "+f"((d)[3]) \
        : "r"((a)[0]), "r"((a)[1]), "r"((a)[2]), "r"((a)[3]), \
          "r"((bb)[0]), "r"((bb)[1]))

__device__ __forceinline__ uint32_t smem_u32(const void* p) {
    uint32_t a;
    asm("{ .reg .u64 t; cvta.to.shared.u64 t, %1; cvt.u32.u64 %0, t; }" : "=r"(a) : "l"(p));
    return a;
}
__device__ __forceinline__ void ldsm_x4(uint32_t& r0, uint32_t& r1,
                                        uint32_t& r2, uint32_t& r3, uint32_t addr) {
    asm volatile("ldmatrix.sync.aligned.m8n8.x4.shared.b16 {%0,%1,%2,%3}, [%4];"
                 : "=r"(r0), "=r"(r1), "=r"(r2), "=r"(r3) : "r"(addr));
}
__device__ __forceinline__ void ldsm_x4_trans(uint32_t& r0, uint32_t& r1,
                                              uint32_t& r2, uint32_t& r3, uint32_t addr) {
    asm volatile("ldmatrix.sync.aligned.m8n8.x4.trans.shared.b16 {%0,%1,%2,%3}, [%4];"
                 : "=r"(r0), "=r"(r1), "=r"(r2), "=r"(r3) : "r"(addr));
}

// ---------------- kernel 0: zero accumulators ----------------
__global__ void k_zero() {
    int i = blockIdx.x * blockDim.x + threadIdx.x;
    if (i < B * K * C) g_sums_x[i] = 0.f;
    if (i < C * C)     g_G[i] = 0.f;
    if (i < B * K)     g_cnt[i] = 0.f;
}

// ---------------- kernel 0.5: prep w^T hi/lo (pitch 136) ----------------
__global__ void k_wprep(const float* __restrict__ w) {
    int i = blockIdx.x * 256 + threadIdx.x;
    if (i < C * C) {
        int c = i >> 7, d = i & 127;
        float v = w[i];
        __nv_bfloat16 h = __float2bfloat16(v);
        g_wh[d * 136 + c] = h;
        g_wl[d * 136 + c] = __float2bfloat16(v - __bfloat162float(h));
    }
}

// ---------------- kernel MM: M = W @ W^T ----------------
__global__ void k_MM(const float* __restrict__ Wm) {
    __shared__ float wi[C];
    int i = blockIdx.x, t = threadIdx.x;
    wi[t] = Wm[i * C + t];
    __syncthreads();
    float acc = 0.f;
#pragma unroll 8
    for (int c = 0; c < C; c++) acc += wi[c] * Wm[t * C + c];
    g_M[i * C + t] = acc;
}

// ================= kernel 1: fused stats pass (G, segment sums, counts) =================
// grid 128 (8 b x 16 segs of 4096 px), 512 threads, 32 chunks of 128 pixels.
// pitch 136 (272 B rows, 16B-aligned); fragments loaded via ldmatrix.x4.
#define P1_PITCH 136
#define P1_XH 0
#define P1_XL 34816
#define P1_OH 69632
#define P1_TOTAL 87040

__global__ __launch_bounds__(512, 1) void k_pass1(const float* __restrict__ x,
                                                  const int* __restrict__ idx) {
    extern __shared__ char smem[];
    __nv_bfloat16* Xh = (__nv_bfloat16*)(smem + P1_XH);
    __nv_bfloat16* Xl = (__nv_bfloat16*)(smem + P1_XL);
    __nv_bfloat16* OH = (__nv_bfloat16*)(smem + P1_OH);
    __shared__ int   sidx[128];
    __shared__ float hcnt[K];

    int tid = threadIdx.x;
    int b   = blockIdx.x >> 4;
    int seg = blockIdx.x & 15;
    int lane = tid & 31, wid = tid >> 5;
    int gid = lane >> 2, tig = lane & 3;
    int dbase  = (wid & 3) * 32;     // G m-tile (rows c1)
    int msbase = (wid & 3) * 16;     // S m-tile (rows k)
    int pbase  = (wid >> 2) * 32;    // n-tile (cols c2 / c)

    if (tid < K) hcnt[tid] = 0.f;

    // ldmatrix lane->pointer offsets
    uint32_t xh_base = smem_u32(Xh);
    uint32_t xl_base = smem_u32(Xl);
    uint32_t oh_base = smem_u32(OH);
    int ldrow_a = (lane & 7) + ((lane >> 3) & 1) * 8;   // A: bit3 -> row+8
    int koff_a  = ((lane >> 4) & 1) * 16;               // A: bit4 -> k+8 (bytes)
    int ldrow_b = (lane & 7) + ((lane >> 4) & 1) * 8;   // B: bit4 -> row+8
    int koff_b  = ((lane >> 3) & 1) * 16;               // B: bit3 -> k+8
    uint32_t a_off = (uint32_t)((dbase + ldrow_a) * 272 + koff_a);
    uint32_t o_off = oh_base + (uint32_t)((msbase + ldrow_a) * 272 + koff_a);
    uint32_t b_off = (uint32_t)((pbase + ldrow_b) * 272 + koff_b);

    float Dg[2][4][4];
    float Ds[4][4];
#pragma unroll
    for (int mf = 0; mf < 2; mf++)
#pragma unroll
        for (int nf = 0; nf < 4; nf++)
#pragma unroll
            for (int q = 0; q < 4; q++) Dg[mf][nf][q] = 0.f;
#pragma unroll
    for (int nf = 0; nf < 4; nf++)
#pragma unroll
        for (int q = 0; q < 4; q++) Ds[nf][q] = 0.f;

    const float* xb = x + (size_t)b * C * HW + seg * 4096;
    const int*   ib = idx + b * HW + seg * 4096;

    for (int ch = 0; ch < 32; ch++) {
        __syncthreads();
        if (tid < 128) sidx[tid] = ib[ch * 128 + tid];
        for (int i = tid; i < 4352; i += 512) ((uint32_t*)OH)[i] = 0u;
        for (int e = tid; e < 4096; e += 512) {
            int row = e >> 5, p4 = (e & 31) * 4;
            float4 v = *(const float4*)(xb + (size_t)row * HW + ch * 128 + p4);
            __nv_bfloat162 h0 = __floats2bfloat162_rn(v.x, v.y);
            __nv_bfloat162 h1 = __floats2bfloat162_rn(v.z, v.w);
            float l0 = v.x - __bfloat162float(h0.x);
            float l1 = v.y - __bfloat162float(h0.y);
            float l2 = v.z - __bfloat162float(h1.x);
            float l3 = v.w - __bfloat162float(h1.y);
            __nv_bfloat162 g0 = __floats2bfloat162_rn(l0, l1);
            __nv_bfloat162 g1 = __floats2bfloat162_rn(l2, l3);
            uint2 hp, lp;
            hp.x = *(uint32_t*)&h0; hp.y = *(uint32_t*)&h1;
            lp.x = *(uint32_t*)&g0; lp.y = *(uint32_t*)&g1;
            *(uint2*)&Xh[row * P1_PITCH + p4] = hp;
            *(uint2*)&Xl[row * P1_PITCH + p4] = lp;
        }
        __syncthreads();
        if (tid < 128) {
            int k = sidx[tid];
            OH[k * P1_PITCH + tid] = __float2bfloat16(1.0f);
            atomicAdd(&hcnt[k], 1.f);
        }
        __syncthreads();

#pragma unroll
        for (int ks = 0; ks < 8; ks++) {
            uint32_t kb = (uint32_t)(32 * ks);
            uint32_t ah[2][4], ao[4];
            uint32_t bh[4][2], bl[4][2];
            ldsm_x4(ah[0][0], ah[0][1], ah[0][2], ah[0][3], xh_base + a_off + kb);
            ldsm_x4(ah[1][0], ah[1][1], ah[1][2], ah[1][3], xh_base + a_off + 4352 + kb);
            ldsm_x4(ao[0], ao[1], ao[2], ao[3], o_off + kb);
            ldsm_x4(bh[0][0], bh[0][1], bh[1][0], bh[1][1], xh_base + b_off + kb);
            ldsm_x4(bh[2][0], bh[2][1], bh[3][0], bh[3][1], xh_base + b_off + 4352 + kb);
            ldsm_x4(bl[0][0], bl[0][1], bl[1][0], bl[1][1], xl_base + b_off + kb);
            ldsm_x4(bl[2][0], bl[2][1], bl[3][0], bl[3][1], xl_base + b_off + 4352 + kb);
#pragma unroll
            for (int mf = 0; mf < 2; mf++)
#pragma unroll
                for (int nf = 0; nf < 4; nf++)
                    MMA_BF16(Dg[mf][nf], ah[mf], bh[nf]);
#pragma unroll
            for (int nf = 0; nf < 4; nf++) {
                MMA_BF16(Ds[nf], ao, bh[nf]);
                MMA_BF16(Ds[nf], ao, bl[nf]);
            }
        }
    }

    // ---- flush partials ----
#pragma unroll
    for (int mf = 0; mf < 2; mf++)
#pragma unroll
        for (int nf = 0; nf < 4; nf++) {
            int r0 = dbase + mf * 16 + gid;
            int cn = pbase + nf * 8 + 2 * tig;
            atomicAdd(&g_G[r0 * C + cn],           Dg[mf][nf][0]);
            atomicAdd(&g_G[r0 * C + cn + 1],       Dg[mf][nf][1]);
            atomicAdd(&g_G[(r0 + 8) * C + cn],     Dg[mf][nf][2]);
            atomicAdd(&g_G[(r0 + 8) * C + cn + 1], Dg[mf][nf][3]);
        }
#pragma unroll
    for (int nf = 0; nf < 4; nf++) {
        int m0 = msbase + gid;
        int cn = pbase + nf * 8 + 2 * tig;
        atomicAdd(&g_sums_x[(b * K + m0) * C + cn],           Ds[nf][0]);
        atomicAdd(&g_sums_x[(b * K + m0) * C + cn + 1],       Ds[nf][1]);
        atomicAdd(&g_sums_x[(b * K + m0 + 8) * C + cn],       Ds[nf][2]);
        atomicAdd(&g_sums_x[(b * K + m0 + 8) * C + cn + 1],   Ds[nf][3]);
    }
    __syncthreads();
    if (tid < K) atomicAdd(&g_cnt[b * K + tid], hcnt[tid]);
}

// ---------------- kernel sm: sumsq (grid [0,128)) | means (grid [128,640)) ----------------
__global__ void k_sm(const float* __restrict__ w) {
    int blk = blockIdx.x;
    int t = threadIdx.x;
    if (blk < 128) {
        __shared__ float wcol[C];
        __shared__ float red[C];
        int d = blk;
        wcol[t] = w[t * C + d];
        __syncthreads();
        float acc = 0.f;
#pragma unroll 8
        for (int c2 = 0; c2 < C; c2++) acc += g_G[t * C + c2] * wcol[c2];
        red[t] = acc * wcol[t];
        __syncthreads();
        for (int s = 64; s > 0; s >>= 1) {
            if (t < s) red[t] += red[t + s];
            __syncthreads();
        }
        if (t == 0) g_sumsq[d] = red[0];
    } else {
        __shared__ float s[C];
        int bk = blk - 128;
        s[t] = g_sums_x[bk * C + t];
        __syncthreads();
        float cnt = g_cnt[bk];
        float denom = (cnt == 0.f) ? 1.f : cnt;
        float acc = 0.f;
#pragma unroll 8
        for (int c = 0; c < C; c++) acc += s[c] * w[c * C + t];
        g_means[bk * C + t] = acc / denom;
    }
}

// ---------------- kernel 5: Y[b,k,d] = means[b,k,:] @ M ----------------
__global__ void k_Y() {
    __shared__ float ms[C];
    int bk = blockIdx.x;
    int d = threadIdx.x;
    ms[d] = g_means[bk * C + d];
    __syncthreads();
    float acc = 0.f;
#pragma unroll 8
    for (int c = 0; c < C; c++) acc += ms[c] * g_M[c * C + d];
    g_Y[bk * C + d] = acc;
}

// ---------------- kernel 6: adjacency + adj_means ----------------
__global__ __launch_bounds__(256) void k_adj(const float* __restrict__ adj_mask) {
    __shared__ float msm[K][C + 1];
    __shared__ float gq[K];
    int b = blockIdx.x, tid = threadIdx.x;
    const float* mb = g_means + b * K * C;
    const float* yb = g_Y + b * K * C;

    for (int i = tid; i < K * C; i += 256) msm[i >> 7][i & 127] = mb[i];
    __syncthreads();

    if (tid < K) {
        float a = 0.f;
#pragma unroll 8
        for (int d = 0; d < C; d++) a += yb[tid * C + d] * msm[tid][d];
        gq[tid] = a;
    }
    __syncthreads();

    for (int i = tid; i < K * K; i += 256) {
        int p = i >> 6, q = i & 63;
        float dot = 0.f;
#pragma unroll 8
        for (int d = 0; d < C; d++) dot += yb[p * C + d] * msm[q][d];
        float quad = gq[p] + gq[q] - 2.f * dot;
        g_adj[b * K * K + i] = (p == q) ? 0.f : expf(-quad) * adj_mask[i];
    }
    __syncthreads();

    for (int i = tid; i < K * C; i += 256) {
        int p = i >> 7, d = i & 127;
        const float* arow = g_adj + b * K * K + p * K;
        float acc = 0.f;
#pragma unroll 8
        for (int q = 0; q < K; q++) acc += arow[q] * msm[q][d];
        g_adjm[b * K * C + i] = acc;
    }
}

// ---------------- kernel 7: BN statistics (analytic) ----------------
__global__ void k_bnstats(const float* __restrict__ gamma, const float* __restrict__ beta) {
    int d = threadIdx.x;
    float S1 = 0.f, S2 = 0.f;
    for (int bk = 0; bk < B * K; bk++) {
        float cnt = g_cnt[bk];
        float denom = (cnt == 0.f) ? 1.f : cnt;
        float m = g_means[bk * C + d];
        float am = g_adjm[bk * C + d];
        float sxw = m * denom;
        S1 += sxw + cnt * am;
        S2 += 2.f * am * sxw + cnt * am * am;
    }
    S2 += g_sumsq[d];
    float mu = S1 / NTOT;
    float var = S2 / NTOT - mu * mu;
    float s = gamma[d] * rsqrtf(var + BN_EPS);
    g_s[d] = s;
    g_t[d] = beta[d] - mu * s;
}

// ---------------- kernel 8: bias table bias[b][d][k] = s[d]*adjm[b][k][d] + t[d] ----------------
__global__ void k_bias() {
    int b = blockIdx.x;
    for (int i = threadIdx.x; i < C * K; i += 256) {
        int d = i >> 6, k = i & 63;
        g_bias[b * C * K + i] = fmaf(g_s[d], g_adjm[(b * K + k) * C + d], g_t[d]);
    }
}

// ================= kernel 9: persistent fused GEMM + output =================
// grid 128 (8 b x 16 segs), 512 threads, 32 chunks; A via ldmatrix (pitch 136),
// B via ldmatrix.trans; epilogue stores D fragments directly (32B sectors).
#define A_PITCH 136
#define X_PITCH 136
#define GO_AH 0
#define GO_AL 34816
#define GO_XH 69632
#define GO_XL 104448
#define GO_BIAS 139264
#define GO_TOTAL 172032

__global__ __launch_bounds__(512, 1) void k_gemm_out(const float* __restrict__ x,
                                                     const int* __restrict__ idx,
                                                     float* __restrict__ out) {
    extern __shared__ char smem[];
    __nv_bfloat16* Ah = (__nv_bfloat16*)(smem + GO_AH);
    __nv_bfloat16* Al = (__nv_bfloat16*)(smem + GO_AL);
    __nv_bfloat16* Xh = (__nv_bfloat16*)(smem + GO_XH);
    __nv_bfloat16* Xl = (__nv_bfloat16*)(smem + GO_XL);
    float* bsm = (float*)(smem + GO_BIAS);        // persistent bias table (32 KB)
    __shared__ float ssm[C];
    __shared__ __align__(8) int sidxp[128];

    int tid = threadIdx.x;
    int b   = blockIdx.x >> 4;
    int seg = blockIdx.x & 15;
    const float* xb = x + (size_t)b * C * HW + seg * 4096;
    const int*   ib = idx + b * HW + seg * 4096;
    float* ob = out + (size_t)b * C * HW + seg * 4096;

    if (tid < C) ssm[tid] = g_s[tid];

    // ---- one-time: W hi/lo + bias table ----
    {
        const uint32_t* wh32 = (const uint32_t*)g_wh;
        const uint32_t* wl32 = (const uint32_t*)g_wl;
        uint32_t* ah32 = (uint32_t*)Ah;
        uint32_t* al32 = (uint32_t*)Al;
        for (int i = tid; i < 8704; i += 512) { ah32[i] = wh32[i]; al32[i] = wl32[i]; }
        const float4* gb = (const float4*)(g_bias + b * C * K);
        float4* bs4 = (float4*)bsm;
        for (int i = tid; i < 2048; i += 512) bs4[i] = gb[i];
    }

    int lane = tid & 31, wid = tid >> 5;
    int gid = lane >> 2, tig = lane & 3;
    int dbase = (wid & 3) * 32;
    int pbase = (wid >> 2) * 32;

    uint32_t ah_base = smem_u32(Ah);
    uint32_t al_base = smem_u32(Al);
    uint32_t xh_base = smem_u32(Xh);
    uint32_t xl_base = smem_u32(Xl);
    int ldrow_a = (lane & 7) + ((lane >> 3) & 1) * 8;
    int koff_a  = ((lane >> 4) & 1) * 16;
    uint32_t a_off = (uint32_t)((dbase + ldrow_a) * 272 + koff_a);
    // trans-B (rows = k): groups (k0-7,n0),(k8-15,n0),(k0-7,n0+8),(k8-15,n0+8)
    int lm_off = ((lane & 7) + ((lane >> 3) & 1) * 8) * X_PITCH
               + pbase + ((lane >> 4) & 1) * 8;

    for (int ch = 0; ch < 32; ch++) {
        __syncthreads();    // prev chunk's epilogue reads of sidxp done
        if (tid < 128) sidxp[tid] = ib[ch * 128 + tid];
        for (int e = tid; e < 4096; e += 512) {
            int row = e >> 5, p4 = (e & 31) * 4;
            float4 v = *(const float4*)(xb + (size_t)row * HW + ch * 128 + p4);
            __nv_bfloat162 h0 = __floats2bfloat162_rn(v.x, v.y);
            __nv_bfloat162 h1 = __floats2bfloat162_rn(v.z, v.w);
            float l0 = v.x - __bfloat162float(h0.x);
            float l1 = v.y - __bfloat162float(h0.y);
            float l2 = v.z - __bfloat162float(h1.x);
            float l3 = v.w - __bfloat162float(h1.y);
            __nv_bfloat162 g0 = __floats2bfloat162_rn(l0, l1);
            __nv_bfloat162 g1 = __floats2bfloat162_rn(l2, l3);
            uint2 hp, lp;
            hp.x = *(uint32_t*)&h0; hp.y = *(uint32_t*)&h1;
            lp.x = *(uint32_t*)&g0; lp.y = *(uint32_t*)&g1;
            *(uint2*)&Xh[row * X_PITCH + p4] = hp;
            *(uint2*)&Xl[row * X_PITCH + p4] = lp;
        }
        __syncthreads();

        float D[2][4][4];
#pragma unroll
        for (int mf = 0; mf < 2; mf++)
#pragma unroll
            for (int nf = 0; nf < 4; nf++)
#pragma unroll
                for (int q = 0; q < 4; q++) D[mf][nf][q] = 0.f;

#pragma unroll
        for (int ks = 0; ks < 8; ks++) {
            uint32_t kb = (uint32_t)(32 * ks);
            uint32_t ah[2][4], al[2][4];
            ldsm_x4(ah[0][0], ah[0][1], ah[0][2], ah[0][3], ah_base + a_off + kb);
            ldsm_x4(ah[1][0], ah[1][1], ah[1][2], ah[1][3], ah_base + a_off + 4352 + kb);
            ldsm_x4(al[0][0], al[0][1], al[0][2], al[0][3], al_base + a_off + kb);
            ldsm_x4(al[1][0], al[1][1], al[1][2], al[1][3], al_base + a_off + 4352 + kb);
            uint32_t bh[4][2], bl[4][2];
#pragma unroll
            for (int nfp = 0; nfp < 2; nfp++) {
                uint32_t aoff = (uint32_t)(16 * ks * X_PITCH + lm_off + nfp * 16) * 2;
                ldsm_x4_trans(bh[2 * nfp][0], bh[2 * nfp][1],
                              bh[2 * nfp + 1][0], bh[2 * nfp + 1][1], xh_base + aoff);
                ldsm_x4_trans(bl[2 * nfp][0], bl[2 * nfp][1],
                              bl[2 * nfp + 1][0], bl[2 * nfp + 1][1], xl_base + aoff);
            }
#pragma unroll
            for (int mf = 0; mf < 2; mf++)
#pragma unroll
                for (int nf = 0; nf < 4; nf++) {
                    MMA_BF16(D[mf][nf], ah[mf], bh[nf]);
                    MMA_BF16(D[mf][nf], ah[mf], bl[nf]);
                    MMA_BF16(D[mf][nf], al[mf], bh[nf]);
                }
        }

        // ---- epilogue: direct fragment stores (32B sectors), smem bias gathers ----
#pragma unroll
        for (int mf = 0; mf < 2; mf++) {
            int r0 = dbase + mf * 16 + gid;
            float sA = ssm[r0], sB = ssm[r0 + 8];
            const float* bA = bsm + r0 * 64;
            const float* bBr = bsm + (r0 + 8) * 64;
            float* oA = ob + (size_t)r0 * HW + ch * 128;
            float* oB = ob + (size_t)(r0 + 8) * HW + ch * 128;
#pragma unroll
            for (int nf = 0; nf < 4; nf++) {
                float* dd = D[mf][nf];
                int cn = pbase + nf * 8 + 2 * tig;
                int2 kk = *(const int2*)&sidxp[cn];
                float2 vA, vB;
                vA.x = fmaf(sA, dd[0], bA[kk.x]);
                vA.y = fmaf(sA, dd[1], bA[kk.y]);
                vB.x = fmaf(sB, dd[2], bBr[kk.x]);
                vB.y = fmaf(sB, dd[3], bBr[kk.y]);
                *(float2*)(oA + cn) = vA;
                *(float2*)(oB + cn) = vB;
            }
        }
    }
}

// ---------------- launch (k_pass1 stays launch #4 -> profiled) ----------------
extern "C" void kernel_launch(void* const* d_in, const int* in_sizes, int n_in,
                              void* d_out, int out_size) {
    const float* x        = (const float*)d_in[0];
    const int*   index    = (const int*)d_in[1];
    const float* weight   = (const float*)d_in[2];
    const float* Wm       = (const float*)d_in[3];
    const float* adj_mask = (const float*)d_in[4];
    const float* gamma    = (const float*)d_in[5];
    const float* beta     = (const float*)d_in[6];
    float* out = (float*)d_out;

    cudaFuncSetAttribute(k_pass1,    cudaFuncAttributeMaxDynamicSharedMemorySize, P1_TOTAL);
    cudaFuncSetAttribute(k_gemm_out, cudaFuncAttributeMaxDynamicSharedMemorySize, GO_TOTAL);

    k_zero<<<256, 256>>>();                       // 1
    k_wprep<<<64, 256>>>(weight);                 // 2
    k_MM<<<128, 128>>>(Wm);                       // 3
    k_pass1<<<128, 512, P1_TOTAL>>>(x, index);    // 4  <-- profiled slot
    k_sm<<<640, 128>>>(weight);                   // 5
    k_Y<<<B * K, 128>>>();                        // 6
    k_adj<<<B, 256>>>(adj_mask);                  // 7
    k_bnstats<<<1, 128>>>(gamma, beta);           // 8
    k_bias<<<B, 256>>>();                         // 9
    k_gemm_out<<<128, 512, GO_TOTAL>>>(x, index, out);  // 10
}